// round 5
// baseline (speedup 1.0000x reference)
#include <cuda_runtime.h>
#include <cuda_bf16.h>
#include <math.h>
#include <stdint.h>

// Problem constants
#define T_SEQ 128
#define B_SZ  32
#define H_SZ  512
#define V_SZ  32000
#define G3    1536          // 3*H
#define M_ROWS 4096         // B*T
#define KSPLIT 1536         // folded K: A'=[hi|hi|lo], B'=[hi|lo|hi]

// Scratch (device globals: allocation-free rule)
__device__ __align__(16) float g_xg[(size_t)M_ROWS * G3];          // [m=b*T+t][3H]
__device__ __align__(16) float g_hs[(size_t)T_SEQ * B_SZ * H_SZ];  // [t][b][h]
__device__ __align__(16) __nv_bfloat16 g_ab[(size_t)M_ROWS * KSPLIT];  // A'
__device__ __align__(16) __nv_bfloat16 g_bb[(size_t)V_SZ * KSPLIT];    // B'
__device__ unsigned g_bar;

// ---------- packed fp32x2 helpers ----------
static __device__ __forceinline__ unsigned long long pk2(float lo, float hi) {
    unsigned long long r;
    asm("mov.b64 %0, {%1, %2};" : "=l"(r) : "f"(lo), "f"(hi));
    return r;
}
static __device__ __forceinline__ unsigned long long f2fma(unsigned long long a,
                                                           unsigned long long b,
                                                           unsigned long long c) {
    unsigned long long d;
    asm("fma.rn.f32x2 %0, %1, %2, %3;" : "=l"(d) : "l"(a), "l"(b), "l"(c));
    return d;
}
static __device__ __forceinline__ float2 upk2(unsigned long long v) {
    float2 r;
    asm("mov.b64 {%0, %1}, %2;" : "=f"(r.x), "=f"(r.y) : "l"(v));
    return r;
}
static __device__ __forceinline__ float sigmoidf_(float x) {
    return 1.0f / (1.0f + expf(-x));
}

// ---------- smem / async-copy / mma helpers (baseline PTX only) ----------
static __device__ __forceinline__ uint32_t smem_u32(const void* p) {
    uint32_t a;
    asm("{ .reg .u64 t; cvta.to.shared.u64 t, %1; cvt.u32.u64 %0, t; }"
        : "=r"(a) : "l"(p));
    return a;
}
static __device__ __forceinline__ void cp_async16(uint32_t dst, const void* src) {
    asm volatile("cp.async.cg.shared.global [%0], [%1], 16;" :: "r"(dst), "l"(src));
}
static __device__ __forceinline__ void cp_commit() {
    asm volatile("cp.async.commit_group;");
}
static __device__ __forceinline__ void cp_wait1() {
    asm volatile("cp.async.wait_group 1;" ::: "memory");
}
static __device__ __forceinline__ void ldsm4(uint32_t* r, uint32_t addr) {
    asm volatile("ldmatrix.sync.aligned.m8n8.x4.shared.b16 {%0,%1,%2,%3}, [%4];"
                 : "=r"(r[0]), "=r"(r[1]), "=r"(r[2]), "=r"(r[3]) : "r"(addr));
}
static __device__ __forceinline__ void mma16816(float* c, const uint32_t* a,
                                                uint32_t b0, uint32_t b1) {
    asm volatile(
        "mma.sync.aligned.m16n8k16.row.col.f32.bf16.bf16.f32 "
        "{%0,%1,%2,%3}, {%4,%5,%6,%7}, {%8,%9}, {%0,%1,%2,%3};"
        : "+f"(c[0]), "+f"(c[1]), "+f"(c[2]), "+f"(c[3])
        : "r"(a[0]), "r"(a[1]), "r"(a[2]), "r"(a[3]), "r"(b0), "r"(b1));
}

// =====================================================================
// Kernel 1: embed + input-gate GEMM (fp32 FFMA2)
// =====================================================================
#define BM 128
#define BN 128
#define BK 16
#define LDS_STRIDE 132

__global__ __launch_bounds__(256, 2)
void embed_xg_kernel(const float* __restrict__ emb,
                     const float* __restrict__ w_ih,
                     const float* __restrict__ b_ih,
                     const int*   __restrict__ target)
{
    __shared__ float As[BK * LDS_STRIDE];
    __shared__ float Bs[BK * LDS_STRIDE];

    const int tid = threadIdx.x;
    const int tx = tid & 15;
    const int ty = tid >> 4;
    const int m0 = blockIdx.x * BM;
    const int n0 = blockIdx.y * BN;

    unsigned long long acc[8][4];
#pragma unroll
    for (int i = 0; i < 8; i++)
#pragma unroll
        for (int j = 0; j < 4; j++) acc[i][j] = 0ull;

    for (int k0 = 0; k0 < H_SZ; k0 += BK) {
#pragma unroll
        for (int l = 0; l < 2; l++) {
            int f4  = tid + l * 256;
            int row = f4 >> 2;
            int c   = (f4 & 3) << 2;
            int m = m0 + row;
            int tok = (m & (T_SEQ - 1)) ? target[m - 1] : 1;
            float4 v = *(const float4*)(emb + (size_t)tok * H_SZ + k0 + c);
            As[(c + 0) * LDS_STRIDE + row] = v.x;
            As[(c + 1) * LDS_STRIDE + row] = v.y;
            As[(c + 2) * LDS_STRIDE + row] = v.z;
            As[(c + 3) * LDS_STRIDE + row] = v.w;
            int g = n0 + row;
            float4 w = *(const float4*)(w_ih + (size_t)g * H_SZ + k0 + c);
            Bs[(c + 0) * LDS_STRIDE + row] = w.x;
            Bs[(c + 1) * LDS_STRIDE + row] = w.y;
            Bs[(c + 2) * LDS_STRIDE + row] = w.z;
            Bs[(c + 3) * LDS_STRIDE + row] = w.w;
        }
        __syncthreads();

#pragma unroll
        for (int kk = 0; kk < BK; kk++) {
            const float* Ak = &As[kk * LDS_STRIDE + ty * 8];
            float4 a0 = *(const float4*)(Ak);
            float4 a1 = *(const float4*)(Ak + 4);
            const float* Bk = &Bs[kk * LDS_STRIDE + tx * 8];
            ulonglong2 bl0 = *(const ulonglong2*)(Bk);
            ulonglong2 bl1 = *(const ulonglong2*)(Bk + 4);
            float av[8] = {a0.x, a0.y, a0.z, a0.w, a1.x, a1.y, a1.z, a1.w};
#pragma unroll
            for (int i = 0; i < 8; i++) {
                unsigned long long a2 = pk2(av[i], av[i]);
                acc[i][0] = f2fma(a2, bl0.x, acc[i][0]);
                acc[i][1] = f2fma(a2, bl0.y, acc[i][1]);
                acc[i][2] = f2fma(a2, bl1.x, acc[i][2]);
                acc[i][3] = f2fma(a2, bl1.y, acc[i][3]);
            }
        }
        __syncthreads();
    }

    const int gcol = n0 + tx * 8;
    float4 bi0 = *(const float4*)(b_ih + gcol);
    float4 bi1 = *(const float4*)(b_ih + gcol + 4);
#pragma unroll
    for (int i = 0; i < 8; i++) {
        int m = m0 + ty * 8 + i;
        float2 p0 = upk2(acc[i][0]);
        float2 p1 = upk2(acc[i][1]);
        float2 p2 = upk2(acc[i][2]);
        float2 p3 = upk2(acc[i][3]);
        float4 o0 = {p0.x + bi0.x, p0.y + bi0.y, p1.x + bi0.z, p1.y + bi0.w};
        float4 o1 = {p2.x + bi1.x, p2.y + bi1.y, p3.x + bi1.z, p3.y + bi1.w};
        float* dst = g_xg + (size_t)m * G3 + gcol;
        *(float4*)(dst)     = o0;
        *(float4*)(dst + 4) = o1;
    }
}

// =====================================================================
// Barrier reset
// =====================================================================
__global__ void reset_bar_kernel() { g_bar = 0u; }

// =====================================================================
// Kernel 2: persistent GRU — 512 threads, k-split 4.
//   128 CTAs; CTA owns H dims [4c,4c+4); 12 w_hh rows live in SMEM.
//   Thread = (kh = tid>>7 in 0..3, b = (tid&127)>>2, il = tid&3):
//   partial dot over k in [kh*128, kh*128+128), combined via SMEM.
// =====================================================================
#define WPAD 520
#define HPAD 516
#define GRU_SMEM_FLOATS (12 * WPAD + 32 * HPAD + 128 * 16)

__global__ __launch_bounds__(512, 1)
void gru_persistent_kernel(const float* __restrict__ w_hh,
                           const float* __restrict__ b_hh,
                           const float* __restrict__ enc)
{
    extern __shared__ float dsm[];
    float* ws   = dsm;                           // 12 * WPAD
    float* hsm  = dsm + 12 * WPAD;               // 32 * HPAD
    float* part = dsm + 12 * WPAD + 32 * HPAD;   // [128][16] partials

    const int cta = blockIdx.x;
    const int tid = threadIdx.x;

    // Load this CTA's 12 w_hh rows once (1536 float4 slots / 512 threads)
#pragma unroll
    for (int l = 0; l < 3; l++) {
        int idx = tid + l * 512;
        int rr  = idx >> 7;
        int cc  = (idx & 127) << 2;
        int gate = rr >> 2;
        int il2  = rr & 3;
        int grow = gate * H_SZ + cta * 4 + il2;
        *(float4*)&ws[rr * WPAD + cc] = *(const float4*)(w_hh + (size_t)grow * H_SZ + cc);
    }

    const int kh = tid >> 7;       // 0..3  k-split index
    const int r  = tid & 127;      // (b, il)
    const int b  = r >> 2;
    const int il = r & 3;
    const int i  = cta * 4 + il;
    const int kbase = kh << 7;     // kh*128

    const float bhr = b_hh[i];
    const float bhz = b_hh[H_SZ + i];
    const float bhn = b_hh[2 * H_SZ + i];

    const ulonglong2* wr = (const ulonglong2*)&ws[(0 + il) * WPAD + kbase];
    const ulonglong2* wz = (const ulonglong2*)&ws[(4 + il) * WPAD + kbase];
    const ulonglong2* wn = (const ulonglong2*)&ws[(8 + il) * WPAD + kbase];

    for (int t = 0; t < T_SEQ; t++) {
        const float* hsrc = (t == 0) ? enc : (g_hs + (size_t)(t - 1) * B_SZ * H_SZ);
        __syncthreads();   // protect hsm/part from previous step's readers
        // Cooperative stage of h_{t-1}: 4096 float4 slots / 512 threads
#pragma unroll
        for (int j = 0; j < 8; j++) {
            int s  = tid + j * 512;
            int bb = s >> 7;
            int k4 = (s & 127) << 2;
            float4 v = __ldcg((const float4*)(hsrc + (size_t)bb * H_SZ + k4));
            *(float4*)&hsm[bb * HPAD + k4] = v;
        }
        __syncthreads();

        const float* hp = &hsm[b * HPAD + kbase];
        unsigned long long ar0 = 0ull, ar1 = 0ull;
        unsigned long long az0 = 0ull, az1 = 0ull;
        unsigned long long an0 = 0ull, an1 = 0ull;
#pragma unroll
        for (int k = 0; k < 128; k += 8) {
            ulonglong2 h01 = *(const ulonglong2*)(hp + k);
            ulonglong2 h23 = *(const ulonglong2*)(hp + k + 4);
            ulonglong2 w_r0 = wr[(k >> 2) + 0];
            ulonglong2 w_r1 = wr[(k >> 2) + 1];
            ulonglong2 w_z0 = wz[(k >> 2) + 0];
            ulonglong2 w_z1 = wz[(k >> 2) + 1];
            ulonglong2 w_n0 = wn[(k >> 2) + 0];
            ulonglong2 w_n1 = wn[(k >> 2) + 1];
            ar0 = f2fma(h01.x, w_r0.x, ar0);
            ar1 = f2fma(h01.y, w_r0.y, ar1);
            ar0 = f2fma(h23.x, w_r1.x, ar0);
            ar1 = f2fma(h23.y, w_r1.y, ar1);
            az0 = f2fma(h01.x, w_z0.x, az0);
            az1 = f2fma(h01.y, w_z0.y, az1);
            az0 = f2fma(h23.x, w_z1.x, az0);
            az1 = f2fma(h23.y, w_z1.y, az1);
            an0 = f2fma(h01.x, w_n0.x, an0);
            an1 = f2fma(h01.y, w_n0.y, an1);
            an0 = f2fma(h23.x, w_n1.x, an0);
            an1 = f2fma(h23.y, w_n1.y, an1);
        }
        float2 pr0 = upk2(ar0), pr1 = upk2(ar1);
        float2 pz0 = upk2(az0), pz1 = upk2(az1);
        float2 pn0 = upk2(an0), pn1 = upk2(an1);
        float* pp = &part[r * 16 + kh * 4];
        pp[0] = (pr0.x + pr0.y) + (pr1.x + pr1.y);
        pp[1] = (pz0.x + pz0.y) + (pz1.x + pz1.y);
        pp[2] = (pn0.x + pn0.y) + (pn1.x + pn1.y);
        __syncthreads();

        if (tid < 128) {
            const float* pr = &part[r * 16];
            float hr = pr[0] + pr[4] + pr[8]  + pr[12] + bhr;
            float hz = pr[1] + pr[5] + pr[9]  + pr[13] + bhz;
            float hn = pr[2] + pr[6] + pr[10] + pr[14] + bhn;

            const float* xgp = g_xg + ((size_t)b * T_SEQ + t) * G3;
            float rg = sigmoidf_(xgp[i] + hr);
            float zg = sigmoidf_(xgp[H_SZ + i] + hz);
            float ng = tanhf(xgp[2 * H_SZ + i] + rg * hn);
            float h_new = (1.0f - zg) * ng + zg * hsm[b * HPAD + i];

            g_hs[((size_t)t * B_SZ + b) * H_SZ + i] = h_new;
            __threadfence();   // release this thread's h write
        }

        // ---- grid barrier (all 128 CTAs co-resident) ----
        __syncthreads();
        if (tid == 0) {
            atomicAdd(&g_bar, 1u);
            unsigned tgt = 128u * (unsigned)(t + 1);
            unsigned v;
            do {
                asm volatile("ld.acquire.gpu.u32 %0, [%1];"
                             : "=r"(v) : "l"(&g_bar) : "memory");
            } while (v < tgt);
        }
        __syncthreads();
    }
}

// =====================================================================
// Conversion kernels: fp32 -> bf16 hi/lo split, folded-K layout
// =====================================================================
union BF4 { __nv_bfloat16 h[4]; uint2 u; };

static __device__ __forceinline__ void split4(float4 x, BF4& hi, BF4& lo) {
    hi.h[0] = __float2bfloat16_rn(x.x);
    hi.h[1] = __float2bfloat16_rn(x.y);
    hi.h[2] = __float2bfloat16_rn(x.z);
    hi.h[3] = __float2bfloat16_rn(x.w);
    lo.h[0] = __float2bfloat16_rn(x.x - __bfloat162float(hi.h[0]));
    lo.h[1] = __float2bfloat16_rn(x.y - __bfloat162float(hi.h[1]));
    lo.h[2] = __float2bfloat16_rn(x.z - __bfloat162float(hi.h[2]));
    lo.h[3] = __float2bfloat16_rn(x.w - __bfloat162float(hi.h[3]));
}

__global__ __launch_bounds__(256)
void convert_emb_kernel(const float* __restrict__ emb)
{
    int s = blockIdx.x * 256 + threadIdx.x;
    if (s >= V_SZ * (H_SZ / 4)) return;
    int v  = s >> 7;
    int k4 = (s & 127) << 2;
    float4 x = *(const float4*)(emb + (size_t)v * H_SZ + k4);
    BF4 hi, lo;
    split4(x, hi, lo);
    __nv_bfloat16* row = g_bb + (size_t)v * KSPLIT;
    *(uint2*)(row + k4)        = hi.u;   // seg0: hi
    *(uint2*)(row + 512 + k4)  = lo.u;   // seg1: lo
    *(uint2*)(row + 1024 + k4) = hi.u;   // seg2: hi
}

__global__ __launch_bounds__(256)
void convert_hs_kernel()
{
    int s = blockIdx.x * 256 + threadIdx.x;
    if (s >= M_ROWS * (H_SZ / 4)) return;
    int m  = s >> 7;
    int k4 = (s & 127) << 2;
    float4 x = *(const float4*)(g_hs + (size_t)m * H_SZ + k4);
    BF4 hi, lo;
    split4(x, hi, lo);
    __nv_bfloat16* row = g_ab + (size_t)m * KSPLIT;
    *(uint2*)(row + k4)        = hi.u;   // seg0: hi
    *(uint2*)(row + 512 + k4)  = hi.u;   // seg1: hi
    *(uint2*)(row + 1024 + k4) = lo.u;   // seg2: lo
}

// =====================================================================
// Kernel 3: logits GEMM via mma.sync bf16
//   CTA 256x256, 512 threads (16 warps, 4x4), warp tile 64x64.
//   K chunks of 32, 3-stage cp.async, XOR-swizzled 64B rows (conflict-free).
// =====================================================================
#define LMT 256
#define LNT 256
#define CHK 32
#define NCH (KSPLIT / CHK)       // 48
#define LSTAGES 3
#define ATILE_B (256 * 64)       // 16384
#define STAGE_B (2 * ATILE_B)    // 32768
#define LTOT_B (LSTAGES * STAGE_B)  // 98304

// 64B rows, seg in 0..3 (16B units); XOR swizzle keeps 8 consecutive rows
// in 8 distinct 16B bank slots -> conflict-free ldmatrix.
static __device__ __forceinline__ uint32_t swoff(int row, int kseg) {
    return (uint32_t)((row << 6) + (((kseg ^ (row >> 1)) & 3) << 4));
}

__global__ __launch_bounds__(512, 1)
void logits_mma_kernel(const float* __restrict__ b_out,
                       float* __restrict__ out)
{
    extern __shared__ __align__(128) char lsm[];
    const uint32_t smb = smem_u32(lsm);
    const int tid  = threadIdx.x;
    const int wid  = tid >> 5;
    const int lane = tid & 31;
    const int warp_m = wid >> 2;   // 0..3 (64 rows each)
    const int warp_n = wid & 3;    // 0..3 (64 cols each)
    const int m0 = blockIdx.x * LMT;
    const int n0 = blockIdx.y * LNT;

    // loader mapping: 512 threads x 2 iters cover 256 rows x 4 segs per array
    const int lr0 = tid >> 2;      // 0..127
    const int lsq = tid & 3;       // source 16B seg 0..3

    float c[4][8][4];
#pragma unroll
    for (int i = 0; i < 4; i++)
#pragma unroll
        for (int j = 0; j < 8; j++)
#pragma unroll
            for (int q = 0; q < 4; q++) c[i][j][q] = 0.0f;

    const int lrow = lane & 15;
    const int lkh  = lane >> 4;    // 0..1 (16B k-half)

    // ---- prologue: issue stages 0,1 ----
#pragma unroll
    for (int ch = 0; ch < 2; ch++) {
        uint32_t As = smb + ch * STAGE_B;
        uint32_t Bs = As + ATILE_B;
        const __nv_bfloat16* ag = g_ab + (size_t)m0 * KSPLIT + ch * CHK + lsq * 8;
        const __nv_bfloat16* bg = g_bb + (size_t)n0 * KSPLIT + ch * CHK + lsq * 8;
#pragma unroll
        for (int l = 0; l < 2; l++) {
            int row = lr0 + l * 128;
            cp_async16(As + swoff(row, lsq), ag + (size_t)row * KSPLIT);
            cp_async16(Bs + swoff(row, lsq), bg + (size_t)row * KSPLIT);
        }
        cp_commit();
    }

    for (int ch = 0; ch < NCH; ch++) {
        cp_wait1();
        __syncthreads();

        // issue ch+2 into stage (ch+2)%3 (freed by the barrier above)
        {
            int chn = ch + 2;
            if (chn < NCH) {
                uint32_t As = smb + (chn % LSTAGES) * STAGE_B;
                uint32_t Bs = As + ATILE_B;
                const __nv_bfloat16* ag = g_ab + (size_t)m0 * KSPLIT + chn * CHK + lsq * 8;
                const __nv_bfloat16* bg = g_bb + (size_t)n0 * KSPLIT + chn * CHK + lsq * 8;
#pragma unroll
                for (int l = 0; l < 2; l++) {
                    int row = lr0 + l * 128;
                    cp_async16(As + swoff(row, lsq), ag + (size_t)row * KSPLIT);
                    cp_async16(Bs + swoff(row, lsq), bg + (size_t)row * KSPLIT);
                }
            }
            cp_commit();   // empty groups keep wait_group counting aligned
        }

        // compute on stage ch%3
        uint32_t As = smb + (ch % LSTAGES) * STAGE_B;
        uint32_t Bs = As + ATILE_B;

#pragma unroll
        for (int ks = 0; ks < 2; ks++) {
            const int kseg = ks * 2 + lkh;
            uint32_t a[4][4], bfr[4][4];
#pragma unroll
            for (int mt = 0; mt < 4; mt++)
                ldsm4(a[mt], As + swoff(warp_m * 64 + mt * 16 + lrow, kseg));
#pragma unroll
            for (int ng = 0; ng < 4; ng++)
                ldsm4(bfr[ng], Bs + swoff(warp_n * 64 + ng * 16 + lrow, kseg));
#pragma unroll
            for (int mt = 0; mt < 4; mt++) {
#pragma unroll
                for (int ng = 0; ng < 4; ng++) {
#pragma unroll
                    for (int j = 0; j < 2; j++) {
                        mma16816(c[mt][ng * 2 + j], a[mt],
                                 bfr[ng][j], bfr[ng][j + 2]);
                    }
                }
            }
        }
        __syncthreads();
    }

    // ---- epilogue ----
    const int rr   = lane >> 2;
    const int col2 = (lane & 3) * 2;
    const int ncol0 = n0 + warp_n * 64;
#pragma unroll
    for (int mt = 0; mt < 4; mt++) {
#pragma unroll
        for (int half = 0; half < 2; half++) {
            int m = m0 + warp_m * 64 + mt * 16 + rr + half * 8;
            int bb2 = m & 31;
            int tt  = m >> 5;
            float* dst = out + ((size_t)bb2 * T_SEQ + tt) * V_SZ + ncol0;
#pragma unroll
            for (int nt = 0; nt < 8; nt++) {
                int nc = nt * 8 + col2;
                float2 v;
                v.x = c[mt][nt][half * 2 + 0] + __ldg(b_out + ncol0 + nc);
                v.y = c[mt][nt][half * 2 + 1] + __ldg(b_out + ncol0 + nc + 1);
                *(float2*)(dst + nc) = v;
            }
        }
    }
}

// =====================================================================
// kernel_launch
// =====================================================================
extern "C" void kernel_launch(void* const* d_in, const int* in_sizes, int n_in,
                              void* d_out, int out_size)
{
    const float* emb    = (const float*)d_in[0];  // [V, H]
    const float* w_ih   = (const float*)d_in[1];  // [3H, H]
    const float* w_hh   = (const float*)d_in[2];  // [3H, H]
    const float* b_ih   = (const float*)d_in[3];  // [3H]
    const float* b_hh   = (const float*)d_in[4];  // [3H]
    const float* b_out  = (const float*)d_in[5];  // [V]
    const float* enc    = (const float*)d_in[6];  // [1, B, H]
    const int*   target = (const int*)d_in[7];    // [B, T]
    float* out = (float*)d_out;                   // [B, T, V]

    (void)in_sizes; (void)n_in; (void)out_size;

    static bool attr_done = false;
    if (!attr_done) {
        cudaFuncSetAttribute(gru_persistent_kernel,
                             cudaFuncAttributeMaxDynamicSharedMemorySize,
                             GRU_SMEM_FLOATS * sizeof(float));
        cudaFuncSetAttribute(logits_mma_kernel,
                             cudaFuncAttributeMaxDynamicSharedMemorySize, LTOT_B);
        attr_done = true;
    }

    convert_emb_kernel<<<(V_SZ * (H_SZ / 4) + 255) / 256, 256>>>(emb);

    embed_xg_kernel<<<dim3(M_ROWS / BM, G3 / BN), 256>>>(emb, w_ih, b_ih, target);

    reset_bar_kernel<<<1, 1>>>();
    gru_persistent_kernel<<<128, 512, GRU_SMEM_FLOATS * sizeof(float)>>>(
        w_hh, b_hh, enc);

    convert_hs_kernel<<<(M_ROWS * (H_SZ / 4) + 255) / 256, 256>>>();

    logits_mma_kernel<<<dim3(M_ROWS / LMT, V_SZ / LNT), 512, LTOT_B>>>(b_out, out);
}

// round 6
// speedup vs baseline: 1.9018x; 1.9018x over previous
#include <cuda_runtime.h>
#include <cuda_bf16.h>
#include <math.h>
#include <stdint.h>

// Problem constants
#define T_SEQ 128
#define B_SZ  32
#define H_SZ  512
#define V_SZ  32000
#define G3    1536          // 3*H
#define M_ROWS 4096         // B*T
#define KSPLIT 1536         // folded K: A'=[hi|hi|lo], B'=[hi|lo|hi]

// Scratch (device globals: allocation-free rule)
__device__ __align__(16) float g_xg[(size_t)M_ROWS * G3];          // [m=b*T+t][3H]
__device__ __align__(16) float g_hs[(size_t)T_SEQ * B_SZ * H_SZ];  // [t][b][h]
__device__ __align__(16) __nv_bfloat16 g_ab[(size_t)M_ROWS * KSPLIT];  // A'
__device__ __align__(16) __nv_bfloat16 g_bb[(size_t)V_SZ * KSPLIT];    // B'
__device__ unsigned g_bar;

// ---------- packed fp32x2 helpers ----------
static __device__ __forceinline__ unsigned long long pk2(float lo, float hi) {
    unsigned long long r;
    asm("mov.b64 %0, {%1, %2};" : "=l"(r) : "f"(lo), "f"(hi));
    return r;
}
static __device__ __forceinline__ unsigned long long f2fma(unsigned long long a,
                                                           unsigned long long b,
                                                           unsigned long long c) {
    unsigned long long d;
    asm("fma.rn.f32x2 %0, %1, %2, %3;" : "=l"(d) : "l"(a), "l"(b), "l"(c));
    return d;
}
static __device__ __forceinline__ float2 upk2(unsigned long long v) {
    float2 r;
    asm("mov.b64 {%0, %1}, %2;" : "=f"(r.x), "=f"(r.y) : "l"(v));
    return r;
}
static __device__ __forceinline__ float sigmoidf_(float x) {
    return 1.0f / (1.0f + expf(-x));
}

// ---------- smem / async-copy / mma helpers (baseline PTX only) ----------
static __device__ __forceinline__ uint32_t smem_u32(const void* p) {
    uint32_t a;
    asm("{ .reg .u64 t; cvta.to.shared.u64 t, %1; cvt.u32.u64 %0, t; }"
        : "=r"(a) : "l"(p));
    return a;
}
static __device__ __forceinline__ void cp_async16(uint32_t dst, const void* src) {
    asm volatile("cp.async.cg.shared.global [%0], [%1], 16;" :: "r"(dst), "l"(src));
}
static __device__ __forceinline__ void cp_commit() {
    asm volatile("cp.async.commit_group;");
}
static __device__ __forceinline__ void cp_wait2() {
    asm volatile("cp.async.wait_group 2;" ::: "memory");
}
static __device__ __forceinline__ void ldsm4(uint32_t* r, uint32_t addr) {
    asm volatile("ldmatrix.sync.aligned.m8n8.x4.shared.b16 {%0,%1,%2,%3}, [%4];"
                 : "=r"(r[0]), "=r"(r[1]), "=r"(r[2]), "=r"(r[3]) : "r"(addr));
}
static __device__ __forceinline__ void mma16816(float* c, const uint32_t* a,
                                                uint32_t b0, uint32_t b1) {
    asm volatile(
        "mma.sync.aligned.m16n8k16.row.col.f32.bf16.bf16.f32 "
        "{%0,%1,%2,%3}, {%4,%5,%6,%7}, {%8,%9}, {%0,%1,%2,%3};"
        : "+f"(c[0]), "+f"(c[1]), "+f"(c[2]), "+f"(c[3])
        : "r"(a[0]), "r"(a[1]), "r"(a[2]), "r"(a[3]), "r"(b0), "r"(b1));
}

// =====================================================================
// Kernel 1: embed + input-gate GEMM (fp32 FFMA2)
// =====================================================================
#define BM 128
#define BN 128
#define BK 16
#define LDS_STRIDE 132

__global__ __launch_bounds__(256, 2)
void embed_xg_kernel(const float* __restrict__ emb,
                     const float* __restrict__ w_ih,
                     const float* __restrict__ b_ih,
                     const int*   __restrict__ target)
{
    __shared__ float As[BK * LDS_STRIDE];
    __shared__ float Bs[BK * LDS_STRIDE];

    const int tid = threadIdx.x;
    const int tx = tid & 15;
    const int ty = tid >> 4;
    const int m0 = blockIdx.x * BM;
    const int n0 = blockIdx.y * BN;

    unsigned long long acc[8][4];
#pragma unroll
    for (int i = 0; i < 8; i++)
#pragma unroll
        for (int j = 0; j < 4; j++) acc[i][j] = 0ull;

    for (int k0 = 0; k0 < H_SZ; k0 += BK) {
#pragma unroll
        for (int l = 0; l < 2; l++) {
            int f4  = tid + l * 256;
            int row = f4 >> 2;
            int c   = (f4 & 3) << 2;
            int m = m0 + row;
            int tok = (m & (T_SEQ - 1)) ? target[m - 1] : 1;
            float4 v = *(const float4*)(emb + (size_t)tok * H_SZ + k0 + c);
            As[(c + 0) * LDS_STRIDE + row] = v.x;
            As[(c + 1) * LDS_STRIDE + row] = v.y;
            As[(c + 2) * LDS_STRIDE + row] = v.z;
            As[(c + 3) * LDS_STRIDE + row] = v.w;
            int g = n0 + row;
            float4 w = *(const float4*)(w_ih + (size_t)g * H_SZ + k0 + c);
            Bs[(c + 0) * LDS_STRIDE + row] = w.x;
            Bs[(c + 1) * LDS_STRIDE + row] = w.y;
            Bs[(c + 2) * LDS_STRIDE + row] = w.z;
            Bs[(c + 3) * LDS_STRIDE + row] = w.w;
        }
        __syncthreads();

#pragma unroll
        for (int kk = 0; kk < BK; kk++) {
            const float* Ak = &As[kk * LDS_STRIDE + ty * 8];
            float4 a0 = *(const float4*)(Ak);
            float4 a1 = *(const float4*)(Ak + 4);
            const float* Bk = &Bs[kk * LDS_STRIDE + tx * 8];
            ulonglong2 bl0 = *(const ulonglong2*)(Bk);
            ulonglong2 bl1 = *(const ulonglong2*)(Bk + 4);
            float av[8] = {a0.x, a0.y, a0.z, a0.w, a1.x, a1.y, a1.z, a1.w};
#pragma unroll
            for (int i = 0; i < 8; i++) {
                unsigned long long a2 = pk2(av[i], av[i]);
                acc[i][0] = f2fma(a2, bl0.x, acc[i][0]);
                acc[i][1] = f2fma(a2, bl0.y, acc[i][1]);
                acc[i][2] = f2fma(a2, bl1.x, acc[i][2]);
                acc[i][3] = f2fma(a2, bl1.y, acc[i][3]);
            }
        }
        __syncthreads();
    }

    const int gcol = n0 + tx * 8;
    float4 bi0 = *(const float4*)(b_ih + gcol);
    float4 bi1 = *(const float4*)(b_ih + gcol + 4);
#pragma unroll
    for (int i = 0; i < 8; i++) {
        int m = m0 + ty * 8 + i;
        float2 p0 = upk2(acc[i][0]);
        float2 p1 = upk2(acc[i][1]);
        float2 p2 = upk2(acc[i][2]);
        float2 p3 = upk2(acc[i][3]);
        float4 o0 = {p0.x + bi0.x, p0.y + bi0.y, p1.x + bi0.z, p1.y + bi0.w};
        float4 o1 = {p2.x + bi1.x, p2.y + bi1.y, p3.x + bi1.z, p3.y + bi1.w};
        float* dst = g_xg + (size_t)m * G3 + gcol;
        *(float4*)(dst)     = o0;
        *(float4*)(dst + 4) = o1;
    }
}

// =====================================================================
// Barrier reset
// =====================================================================
__global__ void reset_bar_kernel() { g_bar = 0u; }

// =====================================================================
// Kernel 2: persistent GRU — 512 threads, k-split 4, fused bf16 output.
//   Single tid==0 release fence per step (R4-proven barrier pattern).
// =====================================================================
#define WPAD 520
#define HPAD 516
#define GRU_SMEM_FLOATS (12 * WPAD + 32 * HPAD + 128 * 16)

__global__ __launch_bounds__(512, 1)
void gru_persistent_kernel(const float* __restrict__ w_hh,
                           const float* __restrict__ b_hh,
                           const float* __restrict__ enc)
{
    extern __shared__ float dsm[];
    float* ws   = dsm;                           // 12 * WPAD
    float* hsm  = dsm + 12 * WPAD;               // 32 * HPAD
    float* part = dsm + 12 * WPAD + 32 * HPAD;   // [128][16] partials

    const int cta = blockIdx.x;
    const int tid = threadIdx.x;

    // Load this CTA's 12 w_hh rows once (1536 float4 slots / 512 threads)
#pragma unroll
    for (int l = 0; l < 3; l++) {
        int idx = tid + l * 512;
        int rr  = idx >> 7;
        int cc  = (idx & 127) << 2;
        int gate = rr >> 2;
        int il2  = rr & 3;
        int grow = gate * H_SZ + cta * 4 + il2;
        *(float4*)&ws[rr * WPAD + cc] = *(const float4*)(w_hh + (size_t)grow * H_SZ + cc);
    }

    const int kh = tid >> 7;       // 0..3  k-split index
    const int r  = tid & 127;      // (b, il)
    const int b  = r >> 2;
    const int il = r & 3;
    const int i  = cta * 4 + il;
    const int kbase = kh << 7;

    const float bhr = b_hh[i];
    const float bhz = b_hh[H_SZ + i];
    const float bhn = b_hh[2 * H_SZ + i];

    const ulonglong2* wr = (const ulonglong2*)&ws[(0 + il) * WPAD + kbase];
    const ulonglong2* wz = (const ulonglong2*)&ws[(4 + il) * WPAD + kbase];
    const ulonglong2* wn = (const ulonglong2*)&ws[(8 + il) * WPAD + kbase];

    for (int t = 0; t < T_SEQ; t++) {
        const float* hsrc = (t == 0) ? enc : (g_hs + (size_t)(t - 1) * B_SZ * H_SZ);
        __syncthreads();   // protect hsm/part from previous step's readers
#pragma unroll
        for (int j = 0; j < 8; j++) {
            int s  = tid + j * 512;
            int bb = s >> 7;
            int k4 = (s & 127) << 2;
            float4 v = __ldcg((const float4*)(hsrc + (size_t)bb * H_SZ + k4));
            *(float4*)&hsm[bb * HPAD + k4] = v;
        }
        __syncthreads();

        const float* hp = &hsm[b * HPAD + kbase];
        unsigned long long ar0 = 0ull, ar1 = 0ull;
        unsigned long long az0 = 0ull, az1 = 0ull;
        unsigned long long an0 = 0ull, an1 = 0ull;
#pragma unroll
        for (int k = 0; k < 128; k += 8) {
            ulonglong2 h01 = *(const ulonglong2*)(hp + k);
            ulonglong2 h23 = *(const ulonglong2*)(hp + k + 4);
            ulonglong2 w_r0 = wr[(k >> 2) + 0];
            ulonglong2 w_r1 = wr[(k >> 2) + 1];
            ulonglong2 w_z0 = wz[(k >> 2) + 0];
            ulonglong2 w_z1 = wz[(k >> 2) + 1];
            ulonglong2 w_n0 = wn[(k >> 2) + 0];
            ulonglong2 w_n1 = wn[(k >> 2) + 1];
            ar0 = f2fma(h01.x, w_r0.x, ar0);
            ar1 = f2fma(h01.y, w_r0.y, ar1);
            ar0 = f2fma(h23.x, w_r1.x, ar0);
            ar1 = f2fma(h23.y, w_r1.y, ar1);
            az0 = f2fma(h01.x, w_z0.x, az0);
            az1 = f2fma(h01.y, w_z0.y, az1);
            az0 = f2fma(h23.x, w_z1.x, az0);
            az1 = f2fma(h23.y, w_z1.y, az1);
            an0 = f2fma(h01.x, w_n0.x, an0);
            an1 = f2fma(h01.y, w_n0.y, an1);
            an0 = f2fma(h23.x, w_n1.x, an0);
            an1 = f2fma(h23.y, w_n1.y, an1);
        }
        float2 pr0 = upk2(ar0), pr1 = upk2(ar1);
        float2 pz0 = upk2(az0), pz1 = upk2(az1);
        float2 pn0 = upk2(an0), pn1 = upk2(an1);
        float* pp = &part[r * 16 + kh * 4];
        pp[0] = (pr0.x + pr0.y) + (pr1.x + pr1.y);
        pp[1] = (pz0.x + pz0.y) + (pz1.x + pz1.y);
        pp[2] = (pn0.x + pn0.y) + (pn1.x + pn1.y);
        __syncthreads();

        if (tid < 128) {
            const float* pr = &part[r * 16];
            float hr = pr[0] + pr[4] + pr[8]  + pr[12] + bhr;
            float hz = pr[1] + pr[5] + pr[9]  + pr[13] + bhz;
            float hn = pr[2] + pr[6] + pr[10] + pr[14] + bhn;

            const float* xgp = g_xg + ((size_t)b * T_SEQ + t) * G3;
            float rg = sigmoidf_(xgp[i] + hr);
            float zg = sigmoidf_(xgp[H_SZ + i] + hz);
            float ng = tanhf(xgp[2 * H_SZ + i] + rg * hn);
            float h_new = (1.0f - zg) * ng + zg * hsm[b * HPAD + i];

            g_hs[((size_t)t * B_SZ + b) * H_SZ + i] = h_new;

            // Fused A' emit for the logits GEMM (m = t*32 + b)
            __nv_bfloat16 hv = __float2bfloat16_rn(h_new);
            __nv_bfloat16 lv = __float2bfloat16_rn(h_new - __bfloat162float(hv));
            __nv_bfloat16* arow = g_ab + ((size_t)t * B_SZ + b) * KSPLIT;
            arow[i]        = hv;   // seg0: hi
            arow[512 + i]  = hv;   // seg1: hi
            arow[1024 + i] = lv;   // seg2: lo
        }

        // ---- grid barrier (all 128 CTAs co-resident) ----
        __syncthreads();
        if (tid == 0) {
            __threadfence();   // release (cumulative over CTA writes via syncthreads)
            atomicAdd(&g_bar, 1u);
            unsigned tgt = 128u * (unsigned)(t + 1);
            unsigned v;
            do {
                asm volatile("ld.acquire.gpu.u32 %0, [%1];"
                             : "=r"(v) : "l"(&g_bar) : "memory");
            } while (v < tgt);
        }
        __syncthreads();
    }
}

// =====================================================================
// Conversion kernel: embedding fp32 -> bf16 hi/lo split, folded-K
// =====================================================================
union BF4 { __nv_bfloat16 h[4]; uint2 u; };

static __device__ __forceinline__ void split4(float4 x, BF4& hi, BF4& lo) {
    hi.h[0] = __float2bfloat16_rn(x.x);
    hi.h[1] = __float2bfloat16_rn(x.y);
    hi.h[2] = __float2bfloat16_rn(x.z);
    hi.h[3] = __float2bfloat16_rn(x.w);
    lo.h[0] = __float2bfloat16_rn(x.x - __bfloat162float(hi.h[0]));
    lo.h[1] = __float2bfloat16_rn(x.y - __bfloat162float(hi.h[1]));
    lo.h[2] = __float2bfloat16_rn(x.z - __bfloat162float(hi.h[2]));
    lo.h[3] = __float2bfloat16_rn(x.w - __bfloat162float(hi.h[3]));
}

__global__ __launch_bounds__(256)
void convert_emb_kernel(const float* __restrict__ emb)
{
    int s = blockIdx.x * 256 + threadIdx.x;
    if (s >= V_SZ * (H_SZ / 4)) return;
    int v  = s >> 7;
    int k4 = (s & 127) << 2;
    float4 x = *(const float4*)(emb + (size_t)v * H_SZ + k4);
    BF4 hi, lo;
    split4(x, hi, lo);
    __nv_bfloat16* row = g_bb + (size_t)v * KSPLIT;
    *(uint2*)(row + k4)        = hi.u;   // seg0: hi
    *(uint2*)(row + 512 + k4)  = lo.u;   // seg1: lo
    *(uint2*)(row + 1024 + k4) = hi.u;   // seg2: hi
}

// =====================================================================
// Kernel 3: logits GEMM via mma.sync bf16 (R4 shape + swizzle + 4 stages)
//   CTA 128x128, 256 threads (8 warps 2x4), warp tile 64x32.
//   K chunks of 32, 4-stage cp.async, XOR-swizzled 64B rows.
// =====================================================================
#define LMT 128
#define LNT 128
#define CHK 32
#define NCH (KSPLIT / CHK)       // 48
#define LSTAGES 4
#define ATILE_B (128 * 64)       // 8192
#define STAGE_B (2 * ATILE_B)    // 16384
#define LTOT_B (LSTAGES * STAGE_B)  // 65536

// 64B rows, seg 0..3 (16B units); slot = (4*row + seg^(row>>1)) mod 8 is a
// permutation over 8 consecutive rows -> conflict-free ldmatrix.
static __device__ __forceinline__ uint32_t swoff(int row, int kseg) {
    return (uint32_t)((row << 6) + (((kseg ^ (row >> 1)) & 3) << 4));
}

__global__ __launch_bounds__(256, 2)
void logits_mma_kernel(const float* __restrict__ b_out,
                       float* __restrict__ out)
{
    extern __shared__ __align__(128) char lsm[];
    const uint32_t smb = smem_u32(lsm);
    const int tid  = threadIdx.x;
    const int wid  = tid >> 5;
    const int lane = tid & 31;
    const int warp_m = wid >> 2;   // 0..1 (64 rows)
    const int warp_n = wid & 3;    // 0..3 (32 cols)
    const int m0 = blockIdx.x * LMT;
    const int n0 = blockIdx.y * LNT;

    // loader mapping: 256 threads x 2 iters cover 128 rows x 4 segs per array
    const int lr0 = tid >> 2;      // 0..63
    const int lsq = tid & 3;       // 16B seg 0..3

    float c[4][4][4];
#pragma unroll
    for (int i = 0; i < 4; i++)
#pragma unroll
        for (int j = 0; j < 4; j++)
#pragma unroll
            for (int q = 0; q < 4; q++) c[i][j][q] = 0.0f;

    const int lrow = lane & 15;
    const int lkh  = lane >> 4;    // 0..1 (16B k-half)

    // ---- prologue: issue chunks 0..2 ----
#pragma unroll
    for (int ch = 0; ch < 3; ch++) {
        uint32_t As = smb + ch * STAGE_B;
        uint32_t Bs = As + ATILE_B;
        const __nv_bfloat16* ag = g_ab + (size_t)m0 * KSPLIT + ch * CHK + lsq * 8;
        const __nv_bfloat16* bg = g_bb + (size_t)n0 * KSPLIT + ch * CHK + lsq * 8;
#pragma unroll
        for (int l = 0; l < 2; l++) {
            int row = lr0 + l * 64;
            cp_async16(As + swoff(row, lsq), ag + (size_t)row * KSPLIT);
            cp_async16(Bs + swoff(row, lsq), bg + (size_t)row * KSPLIT);
        }
        cp_commit();
    }

    for (int ch = 0; ch < NCH; ch++) {
        cp_wait2();
        __syncthreads();

        // issue ch+3 into stage (ch+3)%4 == (ch-1)%4 (freed by barrier above)
        {
            int chn = ch + 3;
            if (chn < NCH) {
                uint32_t As = smb + (chn % LSTAGES) * STAGE_B;
                uint32_t Bs = As + ATILE_B;
                const __nv_bfloat16* ag = g_ab + (size_t)m0 * KSPLIT + chn * CHK + lsq * 8;
                const __nv_bfloat16* bg = g_bb + (size_t)n0 * KSPLIT + chn * CHK + lsq * 8;
#pragma unroll
                for (int l = 0; l < 2; l++) {
                    int row = lr0 + l * 64;
                    cp_async16(As + swoff(row, lsq), ag + (size_t)row * KSPLIT);
                    cp_async16(Bs + swoff(row, lsq), bg + (size_t)row * KSPLIT);
                }
            }
            cp_commit();   // empty groups keep wait_group counting aligned
        }

        // compute on stage ch%4
        uint32_t As = smb + (ch % LSTAGES) * STAGE_B;
        uint32_t Bs = As + ATILE_B;

#pragma unroll
        for (int ks = 0; ks < 2; ks++) {
            const int kseg = ks * 2 + lkh;
            uint32_t a[4][4], bfr[2][4];
#pragma unroll
            for (int mt = 0; mt < 4; mt++)
                ldsm4(a[mt], As + swoff(warp_m * 64 + mt * 16 + lrow, kseg));
#pragma unroll
            for (int ng = 0; ng < 2; ng++)
                ldsm4(bfr[ng], Bs + swoff(warp_n * 32 + ng * 16 + lrow, kseg));
#pragma unroll
            for (int mt = 0; mt < 4; mt++) {
#pragma unroll
                for (int nt = 0; nt < 4; nt++) {
                    uint32_t* bv = bfr[nt >> 1];
                    mma16816(c[mt][nt], a[mt], bv[nt & 1], bv[(nt & 1) + 2]);
                }
            }
        }
        __syncthreads();
    }

    // ---- epilogue ----
    const int rr   = lane >> 2;
    const int col2 = (lane & 3) * 2;
    const int ncol0 = n0 + warp_n * 32;
#pragma unroll
    for (int mt = 0; mt < 4; mt++) {
#pragma unroll
        for (int half = 0; half < 2; half++) {
            int m = m0 + warp_m * 64 + mt * 16 + rr + half * 8;
            int bb2 = m & 31;
            int tt  = m >> 5;
            float* dst = out + ((size_t)bb2 * T_SEQ + tt) * V_SZ + ncol0;
#pragma unroll
            for (int nt = 0; nt < 4; nt++) {
                int nc = nt * 8 + col2;
                float2 v;
                v.x = c[mt][nt][half * 2 + 0] + __ldg(b_out + ncol0 + nc);
                v.y = c[mt][nt][half * 2 + 1] + __ldg(b_out + ncol0 + nc + 1);
                *(float2*)(dst + nc) = v;
            }
        }
    }
}

// =====================================================================
// kernel_launch
// =====================================================================
extern "C" void kernel_launch(void* const* d_in, const int* in_sizes, int n_in,
                              void* d_out, int out_size)
{
    const float* emb    = (const float*)d_in[0];  // [V, H]
    const float* w_ih   = (const float*)d_in[1];  // [3H, H]
    const float* w_hh   = (const float*)d_in[2];  // [3H, H]
    const float* b_ih   = (const float*)d_in[3];  // [3H]
    const float* b_hh   = (const float*)d_in[4];  // [3H]
    const float* b_out  = (const float*)d_in[5];  // [V]
    const float* enc    = (const float*)d_in[6];  // [1, B, H]
    const int*   target = (const int*)d_in[7];    // [B, T]
    float* out = (float*)d_out;                   // [B, T, V]

    (void)in_sizes; (void)n_in; (void)out_size;

    static bool attr_done = false;
    if (!attr_done) {
        cudaFuncSetAttribute(gru_persistent_kernel,
                             cudaFuncAttributeMaxDynamicSharedMemorySize,
                             GRU_SMEM_FLOATS * sizeof(float));
        cudaFuncSetAttribute(logits_mma_kernel,
                             cudaFuncAttributeMaxDynamicSharedMemorySize, LTOT_B);
        attr_done = true;
    }

    convert_emb_kernel<<<(V_SZ * (H_SZ / 4) + 255) / 256, 256>>>(emb);

    embed_xg_kernel<<<dim3(M_ROWS / BM, G3 / BN), 256>>>(emb, w_ih, b_ih, target);

    reset_bar_kernel<<<1, 1>>>();
    gru_persistent_kernel<<<128, 512, GRU_SMEM_FLOATS * sizeof(float)>>>(
        w_hh, b_hh, enc);

    logits_mma_kernel<<<dim3(M_ROWS / LMT, V_SZ / LNT), 256, LTOT_B>>>(b_out, out);
}

// round 7
// speedup vs baseline: 1.9109x; 1.0048x over previous
#include <cuda_runtime.h>
#include <cuda_bf16.h>
#include <math.h>
#include <stdint.h>

// Problem constants
#define T_SEQ 128
#define B_SZ  32
#define H_SZ  512
#define V_SZ  32000
#define G3    1536          // 3*H
#define M_ROWS 4096         // B*T
#define KF    1024          // hi|lo layout: seg0 = hi (k 0..511), seg1 = lo

// Scratch (device globals: allocation-free rule)
__device__ __align__(16) float g_xg[(size_t)M_ROWS * G3];          // [m=b*T+t][3H]
__device__ __align__(16) float g_hs[(size_t)T_SEQ * B_SZ * H_SZ];  // [t][b][h]
__device__ __align__(16) __nv_bfloat16 g_ab[(size_t)M_ROWS * KF];  // A' [hi|lo]
__device__ __align__(16) __nv_bfloat16 g_bb[(size_t)V_SZ * KF];    // B' [hi|lo]
__device__ unsigned g_bar;

// ---------- packed fp32x2 helpers ----------
static __device__ __forceinline__ unsigned long long pk2(float lo, float hi) {
    unsigned long long r;
    asm("mov.b64 %0, {%1, %2};" : "=l"(r) : "f"(lo), "f"(hi));
    return r;
}
static __device__ __forceinline__ unsigned long long f2fma(unsigned long long a,
                                                           unsigned long long b,
                                                           unsigned long long c) {
    unsigned long long d;
    asm("fma.rn.f32x2 %0, %1, %2, %3;" : "=l"(d) : "l"(a), "l"(b), "l"(c));
    return d;
}
static __device__ __forceinline__ float2 upk2(unsigned long long v) {
    float2 r;
    asm("mov.b64 {%0, %1}, %2;" : "=f"(r.x), "=f"(r.y) : "l"(v));
    return r;
}
static __device__ __forceinline__ float sigmoidf_(float x) {
    return 1.0f / (1.0f + expf(-x));
}

// ---------- smem / async-copy / mma helpers (baseline PTX only) ----------
static __device__ __forceinline__ uint32_t smem_u32(const void* p) {
    uint32_t a;
    asm("{ .reg .u64 t; cvta.to.shared.u64 t, %1; cvt.u32.u64 %0, t; }"
        : "=r"(a) : "l"(p));
    return a;
}
static __device__ __forceinline__ void cp_async16(uint32_t dst, const void* src) {
    asm volatile("cp.async.cg.shared.global [%0], [%1], 16;" :: "r"(dst), "l"(src));
}
static __device__ __forceinline__ void cp_commit() {
    asm volatile("cp.async.commit_group;");
}
static __device__ __forceinline__ void cp_wait1() {
    asm volatile("cp.async.wait_group 1;" ::: "memory");
}
static __device__ __forceinline__ void ldsm4(uint32_t* r, uint32_t addr) {
    asm volatile("ldmatrix.sync.aligned.m8n8.x4.shared.b16 {%0,%1,%2,%3}, [%4];"
                 : "=r"(r[0]), "=r"(r[1]), "=r"(r[2]), "=r"(r[3]) : "r"(addr));
}
static __device__ __forceinline__ void mma16816(float* c, const uint32_t* a,
                                                uint32_t b0, uint32_t b1) {
    asm volatile(
        "mma.sync.aligned.m16n8k16.row.col.f32.bf16.bf16.f32 "
        "{%0,%1,%2,%3}, {%4,%5,%6,%7}, {%8,%9}, {%0,%1,%2,%3};"
        : "+f"(c[0]), "+f"(c[1]), "+f"(c[2]), "+f"(c[3])
        : "r"(a[0]), "r"(a[1]), "r"(a[2]), "r"(a[3]), "r"(b0), "r"(b1));
}

// =====================================================================
// Kernel 1: embed + input-gate GEMM (fp32 FFMA2)
// =====================================================================
#define BM 128
#define BN 128
#define BK 16
#define LDS_STRIDE 132

__global__ __launch_bounds__(256, 2)
void embed_xg_kernel(const float* __restrict__ emb,
                     const float* __restrict__ w_ih,
                     const float* __restrict__ b_ih,
                     const int*   __restrict__ target)
{
    __shared__ float As[BK * LDS_STRIDE];
    __shared__ float Bs[BK * LDS_STRIDE];

    const int tid = threadIdx.x;
    const int tx = tid & 15;
    const int ty = tid >> 4;
    const int m0 = blockIdx.x * BM;
    const int n0 = blockIdx.y * BN;

    unsigned long long acc[8][4];
#pragma unroll
    for (int i = 0; i < 8; i++)
#pragma unroll
        for (int j = 0; j < 4; j++) acc[i][j] = 0ull;

    for (int k0 = 0; k0 < H_SZ; k0 += BK) {
#pragma unroll
        for (int l = 0; l < 2; l++) {
            int f4  = tid + l * 256;
            int row = f4 >> 2;
            int c   = (f4 & 3) << 2;
            int m = m0 + row;
            int tok = (m & (T_SEQ - 1)) ? target[m - 1] : 1;
            float4 v = *(const float4*)(emb + (size_t)tok * H_SZ + k0 + c);
            As[(c + 0) * LDS_STRIDE + row] = v.x;
            As[(c + 1) * LDS_STRIDE + row] = v.y;
            As[(c + 2) * LDS_STRIDE + row] = v.z;
            As[(c + 3) * LDS_STRIDE + row] = v.w;
            int g = n0 + row;
            float4 w = *(const float4*)(w_ih + (size_t)g * H_SZ + k0 + c);
            Bs[(c + 0) * LDS_STRIDE + row] = w.x;
            Bs[(c + 1) * LDS_STRIDE + row] = w.y;
            Bs[(c + 2) * LDS_STRIDE + row] = w.z;
            Bs[(c + 3) * LDS_STRIDE + row] = w.w;
        }
        __syncthreads();

#pragma unroll
        for (int kk = 0; kk < BK; kk++) {
            const float* Ak = &As[kk * LDS_STRIDE + ty * 8];
            float4 a0 = *(const float4*)(Ak);
            float4 a1 = *(const float4*)(Ak + 4);
            const float* Bk = &Bs[kk * LDS_STRIDE + tx * 8];
            ulonglong2 bl0 = *(const ulonglong2*)(Bk);
            ulonglong2 bl1 = *(const ulonglong2*)(Bk + 4);
            float av[8] = {a0.x, a0.y, a0.z, a0.w, a1.x, a1.y, a1.z, a1.w};
#pragma unroll
            for (int i = 0; i < 8; i++) {
                unsigned long long a2 = pk2(av[i], av[i]);
                acc[i][0] = f2fma(a2, bl0.x, acc[i][0]);
                acc[i][1] = f2fma(a2, bl0.y, acc[i][1]);
                acc[i][2] = f2fma(a2, bl1.x, acc[i][2]);
                acc[i][3] = f2fma(a2, bl1.y, acc[i][3]);
            }
        }
        __syncthreads();
    }

    const int gcol = n0 + tx * 8;
    float4 bi0 = *(const float4*)(b_ih + gcol);
    float4 bi1 = *(const float4*)(b_ih + gcol + 4);
#pragma unroll
    for (int i = 0; i < 8; i++) {
        int m = m0 + ty * 8 + i;
        float2 p0 = upk2(acc[i][0]);
        float2 p1 = upk2(acc[i][1]);
        float2 p2 = upk2(acc[i][2]);
        float2 p3 = upk2(acc[i][3]);
        float4 o0 = {p0.x + bi0.x, p0.y + bi0.y, p1.x + bi0.z, p1.y + bi0.w};
        float4 o1 = {p2.x + bi1.x, p2.y + bi1.y, p3.x + bi1.z, p3.y + bi1.w};
        float* dst = g_xg + (size_t)m * G3 + gcol;
        *(float4*)(dst)     = o0;
        *(float4*)(dst + 4) = o1;
    }
}

// =====================================================================
// Barrier reset
// =====================================================================
__global__ void reset_bar_kernel() { g_bar = 0u; }

// =====================================================================
// Kernel 2: persistent GRU — 512 threads, k-split 4, fused bf16 emit.
// =====================================================================
#define WPAD 520
#define HPAD 516
#define GRU_SMEM_FLOATS (12 * WPAD + 32 * HPAD + 128 * 16)

__global__ __launch_bounds__(512, 1)
void gru_persistent_kernel(const float* __restrict__ w_hh,
                           const float* __restrict__ b_hh,
                           const float* __restrict__ enc)
{
    extern __shared__ float dsm[];
    float* ws   = dsm;                           // 12 * WPAD
    float* hsm  = dsm + 12 * WPAD;               // 32 * HPAD
    float* part = dsm + 12 * WPAD + 32 * HPAD;   // [128][16] partials

    const int cta = blockIdx.x;
    const int tid = threadIdx.x;

#pragma unroll
    for (int l = 0; l < 3; l++) {
        int idx = tid + l * 512;
        int rr  = idx >> 7;
        int cc  = (idx & 127) << 2;
        int gate = rr >> 2;
        int il2  = rr & 3;
        int grow = gate * H_SZ + cta * 4 + il2;
        *(float4*)&ws[rr * WPAD + cc] = *(const float4*)(w_hh + (size_t)grow * H_SZ + cc);
    }

    const int kh = tid >> 7;
    const int r  = tid & 127;
    const int b  = r >> 2;
    const int il = r & 3;
    const int i  = cta * 4 + il;
    const int kbase = kh << 7;

    const float bhr = b_hh[i];
    const float bhz = b_hh[H_SZ + i];
    const float bhn = b_hh[2 * H_SZ + i];

    const ulonglong2* wr = (const ulonglong2*)&ws[(0 + il) * WPAD + kbase];
    const ulonglong2* wz = (const ulonglong2*)&ws[(4 + il) * WPAD + kbase];
    const ulonglong2* wn = (const ulonglong2*)&ws[(8 + il) * WPAD + kbase];

    for (int t = 0; t < T_SEQ; t++) {
        const float* hsrc = (t == 0) ? enc : (g_hs + (size_t)(t - 1) * B_SZ * H_SZ);
        __syncthreads();
#pragma unroll
        for (int j = 0; j < 8; j++) {
            int s  = tid + j * 512;
            int bb = s >> 7;
            int k4 = (s & 127) << 2;
            float4 v = __ldcg((const float4*)(hsrc + (size_t)bb * H_SZ + k4));
            *(float4*)&hsm[bb * HPAD + k4] = v;
        }
        __syncthreads();

        const float* hp = &hsm[b * HPAD + kbase];
        unsigned long long ar0 = 0ull, ar1 = 0ull;
        unsigned long long az0 = 0ull, az1 = 0ull;
        unsigned long long an0 = 0ull, an1 = 0ull;
#pragma unroll
        for (int k = 0; k < 128; k += 8) {
            ulonglong2 h01 = *(const ulonglong2*)(hp + k);
            ulonglong2 h23 = *(const ulonglong2*)(hp + k + 4);
            ulonglong2 w_r0 = wr[(k >> 2) + 0];
            ulonglong2 w_r1 = wr[(k >> 2) + 1];
            ulonglong2 w_z0 = wz[(k >> 2) + 0];
            ulonglong2 w_z1 = wz[(k >> 2) + 1];
            ulonglong2 w_n0 = wn[(k >> 2) + 0];
            ulonglong2 w_n1 = wn[(k >> 2) + 1];
            ar0 = f2fma(h01.x, w_r0.x, ar0);
            ar1 = f2fma(h01.y, w_r0.y, ar1);
            ar0 = f2fma(h23.x, w_r1.x, ar0);
            ar1 = f2fma(h23.y, w_r1.y, ar1);
            az0 = f2fma(h01.x, w_z0.x, az0);
            az1 = f2fma(h01.y, w_z0.y, az1);
            az0 = f2fma(h23.x, w_z1.x, az0);
            az1 = f2fma(h23.y, w_z1.y, az1);
            an0 = f2fma(h01.x, w_n0.x, an0);
            an1 = f2fma(h01.y, w_n0.y, an1);
            an0 = f2fma(h23.x, w_n1.x, an0);
            an1 = f2fma(h23.y, w_n1.y, an1);
        }
        float2 pr0 = upk2(ar0), pr1 = upk2(ar1);
        float2 pz0 = upk2(az0), pz1 = upk2(az1);
        float2 pn0 = upk2(an0), pn1 = upk2(an1);
        float* pp = &part[r * 16 + kh * 4];
        pp[0] = (pr0.x + pr0.y) + (pr1.x + pr1.y);
        pp[1] = (pz0.x + pz0.y) + (pz1.x + pz1.y);
        pp[2] = (pn0.x + pn0.y) + (pn1.x + pn1.y);
        __syncthreads();

        if (tid < 128) {
            const float* pr = &part[r * 16];
            float hr = pr[0] + pr[4] + pr[8]  + pr[12] + bhr;
            float hz = pr[1] + pr[5] + pr[9]  + pr[13] + bhz;
            float hn = pr[2] + pr[6] + pr[10] + pr[14] + bhn;

            const float* xgp = g_xg + ((size_t)b * T_SEQ + t) * G3;
            float rg = sigmoidf_(xgp[i] + hr);
            float zg = sigmoidf_(xgp[H_SZ + i] + hz);
            float ng = tanhf(xgp[2 * H_SZ + i] + rg * hn);
            float h_new = (1.0f - zg) * ng + zg * hsm[b * HPAD + i];

            g_hs[((size_t)t * B_SZ + b) * H_SZ + i] = h_new;

            // Fused A' emit: [hi|lo] layout (m = t*32 + b)
            __nv_bfloat16 hv = __float2bfloat16_rn(h_new);
            __nv_bfloat16 lv = __float2bfloat16_rn(h_new - __bfloat162float(hv));
            __nv_bfloat16* arow = g_ab + ((size_t)t * B_SZ + b) * KF;
            arow[i]       = hv;   // seg0: hi
            arow[512 + i] = lv;   // seg1: lo
        }

        // ---- grid barrier (all 128 CTAs co-resident) ----
        __syncthreads();
        if (tid == 0) {
            __threadfence();
            atomicAdd(&g_bar, 1u);
            unsigned tgt = 128u * (unsigned)(t + 1);
            unsigned v;
            do {
                asm volatile("ld.acquire.gpu.u32 %0, [%1];"
                             : "=r"(v) : "l"(&g_bar) : "memory");
            } while (v < tgt);
        }
        __syncthreads();
    }
}

// =====================================================================
// Conversion kernel: embedding fp32 -> bf16 [hi|lo]
// =====================================================================
union BF4 { __nv_bfloat16 h[4]; uint2 u; };

static __device__ __forceinline__ void split4(float4 x, BF4& hi, BF4& lo) {
    hi.h[0] = __float2bfloat16_rn(x.x);
    hi.h[1] = __float2bfloat16_rn(x.y);
    hi.h[2] = __float2bfloat16_rn(x.z);
    hi.h[3] = __float2bfloat16_rn(x.w);
    lo.h[0] = __float2bfloat16_rn(x.x - __bfloat162float(hi.h[0]));
    lo.h[1] = __float2bfloat16_rn(x.y - __bfloat162float(hi.h[1]));
    lo.h[2] = __float2bfloat16_rn(x.z - __bfloat162float(hi.h[2]));
    lo.h[3] = __float2bfloat16_rn(x.w - __bfloat162float(hi.h[3]));
}

__global__ __launch_bounds__(256)
void convert_emb_kernel(const float* __restrict__ emb)
{
    int s = blockIdx.x * 256 + threadIdx.x;
    if (s >= V_SZ * (H_SZ / 4)) return;
    int v  = s >> 7;
    int k4 = (s & 127) << 2;
    float4 x = *(const float4*)(emb + (size_t)v * H_SZ + k4);
    BF4 hi, lo;
    split4(x, hi, lo);
    __nv_bfloat16* row = g_bb + (size_t)v * KF;
    *(uint2*)(row + k4)       = hi.u;   // seg0: hi
    *(uint2*)(row + 512 + k4) = lo.u;   // seg1: lo
}

// =====================================================================
// Kernel 3: logits GEMM via mma.sync bf16 — hi/lo staged ONCE per chunk,
//   3 MMA passes (Ahi·Bhi + Alo·Bhi + Ahi·Blo) reuse the staged tiles.
//   CTA 128x128, 256 threads (8 warps 2x4), warp tile 64x32.
//   Base-K chunks of 32 (16 chunks), 3-stage cp.async, XOR swizzle.
// =====================================================================
#define LMT 128
#define LNT 128
#define CHK 32
#define NCH (512 / CHK)          // 16 chunks over base K
#define LSTAGES 3
#define TILE_B (128 * 64)        // one 128x32 bf16 tile = 8192 B
#define STAGE_B (4 * TILE_B)     // AH, AL, BH, BL = 32768 B
#define LTOT_B (LSTAGES * STAGE_B)  // 98304 B

// 64B rows, seg 0..3 (16B units); conflict-free for ldmatrix.
static __device__ __forceinline__ uint32_t swoff(int row, int kseg) {
    return (uint32_t)((row << 6) + (((kseg ^ (row >> 1)) & 3) << 4));
}

__global__ __launch_bounds__(256, 2)
void logits_mma_kernel(const float* __restrict__ b_out,
                       float* __restrict__ out)
{
    extern __shared__ __align__(128) char lsm[];
    const uint32_t smb = smem_u32(lsm);
    const int tid  = threadIdx.x;
    const int wid  = tid >> 5;
    const int lane = tid & 31;
    const int warp_m = wid >> 2;   // 0..1 (64 rows)
    const int warp_n = wid & 3;    // 0..3 (32 cols)
    const int m0 = blockIdx.x * LMT;
    const int n0 = blockIdx.y * LNT;

    const int lr0 = tid >> 2;      // 0..63
    const int lsq = tid & 3;       // 16B seg 0..3

    float c[4][4][4];
#pragma unroll
    for (int i = 0; i < 4; i++)
#pragma unroll
        for (int j = 0; j < 4; j++)
#pragma unroll
            for (int q = 0; q < 4; q++) c[i][j][q] = 0.0f;

    const int lrow = lane & 15;
    const int lkh  = lane >> 4;

    // Source row base pointers (seg-adjusted once)
    const __nv_bfloat16* ah_base = g_ab + (size_t)m0 * KF + lsq * 8;
    const __nv_bfloat16* bh_base = g_bb + (size_t)n0 * KF + lsq * 8;

    // issue one chunk's 4 tiles into stage st
    auto issue = [&](int ch, int st) {
        uint32_t S = smb + st * STAGE_B;
        int kb = ch * CHK;
#pragma unroll
        for (int l = 0; l < 2; l++) {
            int row = lr0 + l * 64;
            uint32_t so = swoff(row, lsq);
            const __nv_bfloat16* ar = ah_base + (size_t)row * KF + kb;
            const __nv_bfloat16* br = bh_base + (size_t)row * KF + kb;
            cp_async16(S + 0 * TILE_B + so, ar);         // A hi
            cp_async16(S + 1 * TILE_B + so, ar + 512);   // A lo
            cp_async16(S + 2 * TILE_B + so, br);         // B hi
            cp_async16(S + 3 * TILE_B + so, br + 512);   // B lo
        }
    };

    // prologue: chunks 0,1
    issue(0, 0); cp_commit();
    issue(1, 1); cp_commit();

    for (int ch = 0; ch < NCH; ch++) {
        cp_wait1();
        __syncthreads();

        int chn = ch + 2;
        if (chn < NCH) issue(chn, chn % LSTAGES);
        cp_commit();   // empty group keeps wait_group counting aligned

        uint32_t S  = smb + (ch % LSTAGES) * STAGE_B;
        uint32_t AH = S;
        uint32_t AL = S + 1 * TILE_B;
        uint32_t BH = S + 2 * TILE_B;
        uint32_t BL = S + 3 * TILE_B;

#pragma unroll
        for (int ks = 0; ks < 2; ks++) {
            const int kseg = ks * 2 + lkh;
            uint32_t ah[4][4], al[4][4], bf[2][4];
            // B hi frags
#pragma unroll
            for (int ng = 0; ng < 2; ng++)
                ldsm4(bf[ng], BH + swoff(warp_n * 32 + ng * 16 + lrow, kseg));
            // A hi frags ; Ahi x Bhi
#pragma unroll
            for (int mt = 0; mt < 4; mt++)
                ldsm4(ah[mt], AH + swoff(warp_m * 64 + mt * 16 + lrow, kseg));
#pragma unroll
            for (int mt = 0; mt < 4; mt++)
#pragma unroll
                for (int nt = 0; nt < 4; nt++) {
                    uint32_t* bv = bf[nt >> 1];
                    mma16816(c[mt][nt], ah[mt], bv[nt & 1], bv[(nt & 1) + 2]);
                }
            // A lo frags ; Alo x Bhi
#pragma unroll
            for (int mt = 0; mt < 4; mt++)
                ldsm4(al[mt], AL + swoff(warp_m * 64 + mt * 16 + lrow, kseg));
#pragma unroll
            for (int mt = 0; mt < 4; mt++)
#pragma unroll
                for (int nt = 0; nt < 4; nt++) {
                    uint32_t* bv = bf[nt >> 1];
                    mma16816(c[mt][nt], al[mt], bv[nt & 1], bv[(nt & 1) + 2]);
                }
            // B lo frags (reuse bf) ; Ahi x Blo
#pragma unroll
            for (int ng = 0; ng < 2; ng++)
                ldsm4(bf[ng], BL + swoff(warp_n * 32 + ng * 16 + lrow, kseg));
#pragma unroll
            for (int mt = 0; mt < 4; mt++)
#pragma unroll
                for (int nt = 0; nt < 4; nt++) {
                    uint32_t* bv = bf[nt >> 1];
                    mma16816(c[mt][nt], ah[mt], bv[nt & 1], bv[(nt & 1) + 2]);
                }
        }
        __syncthreads();
    }

    // ---- epilogue ----
    const int rr   = lane >> 2;
    const int col2 = (lane & 3) * 2;
    const int ncol0 = n0 + warp_n * 32;
#pragma unroll
    for (int mt = 0; mt < 4; mt++) {
#pragma unroll
        for (int half = 0; half < 2; half++) {
            int m = m0 + warp_m * 64 + mt * 16 + rr + half * 8;
            int bb2 = m & 31;
            int tt  = m >> 5;
            float* dst = out + ((size_t)bb2 * T_SEQ + tt) * V_SZ + ncol0;
#pragma unroll
            for (int nt = 0; nt < 4; nt++) {
                int nc = nt * 8 + col2;
                float2 v;
                v.x = c[mt][nt][half * 2 + 0] + __ldg(b_out + ncol0 + nc);
                v.y = c[mt][nt][half * 2 + 1] + __ldg(b_out + ncol0 + nc + 1);
                *(float2*)(dst + nc) = v;
            }
        }
    }
}

// =====================================================================
// kernel_launch
// =====================================================================
extern "C" void kernel_launch(void* const* d_in, const int* in_sizes, int n_in,
                              void* d_out, int out_size)
{
    const float* emb    = (const float*)d_in[0];  // [V, H]
    const float* w_ih   = (const float*)d_in[1];  // [3H, H]
    const float* w_hh   = (const float*)d_in[2];  // [3H, H]
    const float* b_ih   = (const float*)d_in[3];  // [3H]
    const float* b_hh   = (const float*)d_in[4];  // [3H]
    const float* b_out  = (const float*)d_in[5];  // [V]
    const float* enc    = (const float*)d_in[6];  // [1, B, H]
    const int*   target = (const int*)d_in[7];    // [B, T]
    float* out = (float*)d_out;                   // [B, T, V]

    (void)in_sizes; (void)n_in; (void)out_size;

    static bool attr_done = false;
    if (!attr_done) {
        cudaFuncSetAttribute(gru_persistent_kernel,
                             cudaFuncAttributeMaxDynamicSharedMemorySize,
                             GRU_SMEM_FLOATS * sizeof(float));
        cudaFuncSetAttribute(logits_mma_kernel,
                             cudaFuncAttributeMaxDynamicSharedMemorySize, LTOT_B);
        attr_done = true;
    }

    convert_emb_kernel<<<(V_SZ * (H_SZ / 4) + 255) / 256, 256>>>(emb);

    embed_xg_kernel<<<dim3(M_ROWS / BM, G3 / BN), 256>>>(emb, w_ih, b_ih, target);

    reset_bar_kernel<<<1, 1>>>();
    gru_persistent_kernel<<<128, 512, GRU_SMEM_FLOATS * sizeof(float)>>>(
        w_hh, b_hh, enc);

    logits_mma_kernel<<<dim3(M_ROWS / LMT, V_SZ / LNT), 256, LTOT_B>>>(b_out, out);
}

// round 8
// speedup vs baseline: 2.5783x; 1.3493x over previous
#include <cuda_runtime.h>
#include <cuda_fp16.h>
#include <math.h>
#include <stdint.h>

// Problem constants
#define T_SEQ 128
#define B_SZ  32
#define H_SZ  512
#define V_SZ  32000
#define G3    1536          // 3*H
#define M_ROWS 4096         // B*T

// Scratch (device globals: allocation-free rule)
__device__ __align__(16) float g_xg[(size_t)M_ROWS * G3];          // [m=b*T+t][3H]
__device__ __align__(16) float g_hs[(size_t)T_SEQ * B_SZ * H_SZ];  // [t][b][h]
__device__ __align__(16) __half g_ah[(size_t)M_ROWS * H_SZ];       // A fp16 [m][512]
__device__ __align__(16) __half g_bh[(size_t)V_SZ * H_SZ];         // B fp16 [v][512]
__device__ unsigned g_bar;

// ---------- packed fp32x2 helpers ----------
static __device__ __forceinline__ unsigned long long pk2(float lo, float hi) {
    unsigned long long r;
    asm("mov.b64 %0, {%1, %2};" : "=l"(r) : "f"(lo), "f"(hi));
    return r;
}
static __device__ __forceinline__ unsigned long long f2fma(unsigned long long a,
                                                           unsigned long long b,
                                                           unsigned long long c) {
    unsigned long long d;
    asm("fma.rn.f32x2 %0, %1, %2, %3;" : "=l"(d) : "l"(a), "l"(b), "l"(c));
    return d;
}
static __device__ __forceinline__ float2 upk2(unsigned long long v) {
    float2 r;
    asm("mov.b64 {%0, %1}, %2;" : "=f"(r.x), "=f"(r.y) : "l"(v));
    return r;
}
static __device__ __forceinline__ float sigmoidf_(float x) {
    return 1.0f / (1.0f + expf(-x));
}

// ---------- smem / async-copy / mma helpers (baseline PTX only) ----------
static __device__ __forceinline__ uint32_t smem_u32(const void* p) {
    uint32_t a;
    asm("{ .reg .u64 t; cvta.to.shared.u64 t, %1; cvt.u32.u64 %0, t; }"
        : "=r"(a) : "l"(p));
    return a;
}
static __device__ __forceinline__ void cp_async16(uint32_t dst, const void* src) {
    asm volatile("cp.async.cg.shared.global [%0], [%1], 16;" :: "r"(dst), "l"(src));
}
static __device__ __forceinline__ void cp_commit() {
    asm volatile("cp.async.commit_group;");
}
static __device__ __forceinline__ void cp_wait1() {
    asm volatile("cp.async.wait_group 1;" ::: "memory");
}
static __device__ __forceinline__ void ldsm4(uint32_t* r, uint32_t addr) {
    asm volatile("ldmatrix.sync.aligned.m8n8.x4.shared.b16 {%0,%1,%2,%3}, [%4];"
                 : "=r"(r[0]), "=r"(r[1]), "=r"(r[2]), "=r"(r[3]) : "r"(addr));
}
static __device__ __forceinline__ void mma16816h(float* c, const uint32_t* a,
                                                 uint32_t b0, uint32_t b1) {
    asm volatile(
        "mma.sync.aligned.m16n8k16.row.col.f32.f16.f16.f32 "
        "{%0,%1,%2,%3}, {%4,%5,%6,%7}, {%8,%9}, {%0,%1,%2,%3};"
        : "+f"(c[0]), "+f"(c[1]), "+f"(c[2]), "+f"(c[3])
        : "r"(a[0]), "r"(a[1]), "r"(a[2]), "r"(a[3]), "r"(b0), "r"(b1));
}

// =====================================================================
// Kernel 1: embed + input-gate GEMM (fp32 FFMA2)
// =====================================================================
#define BM 128
#define BN 128
#define BK 16
#define LDS_STRIDE 132

__global__ __launch_bounds__(256, 2)
void embed_xg_kernel(const float* __restrict__ emb,
                     const float* __restrict__ w_ih,
                     const float* __restrict__ b_ih,
                     const int*   __restrict__ target)
{
    __shared__ float As[BK * LDS_STRIDE];
    __shared__ float Bs[BK * LDS_STRIDE];

    const int tid = threadIdx.x;
    const int tx = tid & 15;
    const int ty = tid >> 4;
    const int m0 = blockIdx.x * BM;
    const int n0 = blockIdx.y * BN;

    unsigned long long acc[8][4];
#pragma unroll
    for (int i = 0; i < 8; i++)
#pragma unroll
        for (int j = 0; j < 4; j++) acc[i][j] = 0ull;

    for (int k0 = 0; k0 < H_SZ; k0 += BK) {
#pragma unroll
        for (int l = 0; l < 2; l++) {
            int f4  = tid + l * 256;
            int row = f4 >> 2;
            int c   = (f4 & 3) << 2;
            int m = m0 + row;
            int tok = (m & (T_SEQ - 1)) ? target[m - 1] : 1;
            float4 v = *(const float4*)(emb + (size_t)tok * H_SZ + k0 + c);
            As[(c + 0) * LDS_STRIDE + row] = v.x;
            As[(c + 1) * LDS_STRIDE + row] = v.y;
            As[(c + 2) * LDS_STRIDE + row] = v.z;
            As[(c + 3) * LDS_STRIDE + row] = v.w;
            int g = n0 + row;
            float4 w = *(const float4*)(w_ih + (size_t)g * H_SZ + k0 + c);
            Bs[(c + 0) * LDS_STRIDE + row] = w.x;
            Bs[(c + 1) * LDS_STRIDE + row] = w.y;
            Bs[(c + 2) * LDS_STRIDE + row] = w.z;
            Bs[(c + 3) * LDS_STRIDE + row] = w.w;
        }
        __syncthreads();

#pragma unroll
        for (int kk = 0; kk < BK; kk++) {
            const float* Ak = &As[kk * LDS_STRIDE + ty * 8];
            float4 a0 = *(const float4*)(Ak);
            float4 a1 = *(const float4*)(Ak + 4);
            const float* Bk = &Bs[kk * LDS_STRIDE + tx * 8];
            ulonglong2 bl0 = *(const ulonglong2*)(Bk);
            ulonglong2 bl1 = *(const ulonglong2*)(Bk + 4);
            float av[8] = {a0.x, a0.y, a0.z, a0.w, a1.x, a1.y, a1.z, a1.w};
#pragma unroll
            for (int i = 0; i < 8; i++) {
                unsigned long long a2 = pk2(av[i], av[i]);
                acc[i][0] = f2fma(a2, bl0.x, acc[i][0]);
                acc[i][1] = f2fma(a2, bl0.y, acc[i][1]);
                acc[i][2] = f2fma(a2, bl1.x, acc[i][2]);
                acc[i][3] = f2fma(a2, bl1.y, acc[i][3]);
            }
        }
        __syncthreads();
    }

    const int gcol = n0 + tx * 8;
    float4 bi0 = *(const float4*)(b_ih + gcol);
    float4 bi1 = *(const float4*)(b_ih + gcol + 4);
#pragma unroll
    for (int i = 0; i < 8; i++) {
        int m = m0 + ty * 8 + i;
        float2 p0 = upk2(acc[i][0]);
        float2 p1 = upk2(acc[i][1]);
        float2 p2 = upk2(acc[i][2]);
        float2 p3 = upk2(acc[i][3]);
        float4 o0 = {p0.x + bi0.x, p0.y + bi0.y, p1.x + bi0.z, p1.y + bi0.w};
        float4 o1 = {p2.x + bi1.x, p2.y + bi1.y, p3.x + bi1.z, p3.y + bi1.w};
        float* dst = g_xg + (size_t)m * G3 + gcol;
        *(float4*)(dst)     = o0;
        *(float4*)(dst + 4) = o1;
    }
}

// =====================================================================
// Barrier reset
// =====================================================================
__global__ void reset_bar_kernel() { g_bar = 0u; }

// =====================================================================
// Kernel 2: persistent GRU — 512 threads, k-split 4, fused fp16 emit.
// =====================================================================
#define WPAD 520
#define HPAD 516
#define GRU_SMEM_FLOATS (12 * WPAD + 32 * HPAD + 128 * 16)

__global__ __launch_bounds__(512, 1)
void gru_persistent_kernel(const float* __restrict__ w_hh,
                           const float* __restrict__ b_hh,
                           const float* __restrict__ enc)
{
    extern __shared__ float dsm[];
    float* ws   = dsm;                           // 12 * WPAD
    float* hsm  = dsm + 12 * WPAD;               // 32 * HPAD
    float* part = dsm + 12 * WPAD + 32 * HPAD;   // [128][16] partials

    const int cta = blockIdx.x;
    const int tid = threadIdx.x;

#pragma unroll
    for (int l = 0; l < 3; l++) {
        int idx = tid + l * 512;
        int rr  = idx >> 7;
        int cc  = (idx & 127) << 2;
        int gate = rr >> 2;
        int il2  = rr & 3;
        int grow = gate * H_SZ + cta * 4 + il2;
        *(float4*)&ws[rr * WPAD + cc] = *(const float4*)(w_hh + (size_t)grow * H_SZ + cc);
    }

    const int kh = tid >> 7;
    const int r  = tid & 127;
    const int b  = r >> 2;
    const int il = r & 3;
    const int i  = cta * 4 + il;
    const int kbase = kh << 7;

    const float bhr = b_hh[i];
    const float bhz = b_hh[H_SZ + i];
    const float bhn = b_hh[2 * H_SZ + i];

    const ulonglong2* wr = (const ulonglong2*)&ws[(0 + il) * WPAD + kbase];
    const ulonglong2* wz = (const ulonglong2*)&ws[(4 + il) * WPAD + kbase];
    const ulonglong2* wn = (const ulonglong2*)&ws[(8 + il) * WPAD + kbase];

    for (int t = 0; t < T_SEQ; t++) {
        const float* hsrc = (t == 0) ? enc : (g_hs + (size_t)(t - 1) * B_SZ * H_SZ);
        __syncthreads();
#pragma unroll
        for (int j = 0; j < 8; j++) {
            int s  = tid + j * 512;
            int bb = s >> 7;
            int k4 = (s & 127) << 2;
            float4 v = __ldcg((const float4*)(hsrc + (size_t)bb * H_SZ + k4));
            *(float4*)&hsm[bb * HPAD + k4] = v;
        }
        __syncthreads();

        const float* hp = &hsm[b * HPAD + kbase];
        unsigned long long ar0 = 0ull, ar1 = 0ull;
        unsigned long long az0 = 0ull, az1 = 0ull;
        unsigned long long an0 = 0ull, an1 = 0ull;
#pragma unroll
        for (int k = 0; k < 128; k += 8) {
            ulonglong2 h01 = *(const ulonglong2*)(hp + k);
            ulonglong2 h23 = *(const ulonglong2*)(hp + k + 4);
            ulonglong2 w_r0 = wr[(k >> 2) + 0];
            ulonglong2 w_r1 = wr[(k >> 2) + 1];
            ulonglong2 w_z0 = wz[(k >> 2) + 0];
            ulonglong2 w_z1 = wz[(k >> 2) + 1];
            ulonglong2 w_n0 = wn[(k >> 2) + 0];
            ulonglong2 w_n1 = wn[(k >> 2) + 1];
            ar0 = f2fma(h01.x, w_r0.x, ar0);
            ar1 = f2fma(h01.y, w_r0.y, ar1);
            ar0 = f2fma(h23.x, w_r1.x, ar0);
            ar1 = f2fma(h23.y, w_r1.y, ar1);
            az0 = f2fma(h01.x, w_z0.x, az0);
            az1 = f2fma(h01.y, w_z0.y, az1);
            az0 = f2fma(h23.x, w_z1.x, az0);
            az1 = f2fma(h23.y, w_z1.y, az1);
            an0 = f2fma(h01.x, w_n0.x, an0);
            an1 = f2fma(h01.y, w_n0.y, an1);
            an0 = f2fma(h23.x, w_n1.x, an0);
            an1 = f2fma(h23.y, w_n1.y, an1);
        }
        float2 pr0 = upk2(ar0), pr1 = upk2(ar1);
        float2 pz0 = upk2(az0), pz1 = upk2(az1);
        float2 pn0 = upk2(an0), pn1 = upk2(an1);
        float* pp = &part[r * 16 + kh * 4];
        pp[0] = (pr0.x + pr0.y) + (pr1.x + pr1.y);
        pp[1] = (pz0.x + pz0.y) + (pz1.x + pz1.y);
        pp[2] = (pn0.x + pn0.y) + (pn1.x + pn1.y);
        __syncthreads();

        if (tid < 128) {
            const float* pr = &part[r * 16];
            float hr = pr[0] + pr[4] + pr[8]  + pr[12] + bhr;
            float hz = pr[1] + pr[5] + pr[9]  + pr[13] + bhz;
            float hn = pr[2] + pr[6] + pr[10] + pr[14] + bhn;

            const float* xgp = g_xg + ((size_t)b * T_SEQ + t) * G3;
            float rg = sigmoidf_(xgp[i] + hr);
            float zg = sigmoidf_(xgp[H_SZ + i] + hz);
            float ng = tanhf(xgp[2 * H_SZ + i] + rg * hn);
            float h_new = (1.0f - zg) * ng + zg * hsm[b * HPAD + i];

            g_hs[((size_t)t * B_SZ + b) * H_SZ + i] = h_new;

            // Fused A emit (fp16) for the logits GEMM (m = t*32 + b)
            g_ah[((size_t)t * B_SZ + b) * H_SZ + i] = __float2half_rn(h_new);
        }

        // ---- grid barrier (all 128 CTAs co-resident) ----
        __syncthreads();
        if (tid == 0) {
            __threadfence();
            atomicAdd(&g_bar, 1u);
            unsigned tgt = 128u * (unsigned)(t + 1);
            unsigned v;
            do {
                asm volatile("ld.acquire.gpu.u32 %0, [%1];"
                             : "=r"(v) : "l"(&g_bar) : "memory");
            } while (v < tgt);
        }
        __syncthreads();
    }
}

// =====================================================================
// Conversion kernel: embedding fp32 -> fp16
// =====================================================================
union HF4 { __half h[4]; uint2 u; };

__global__ __launch_bounds__(256)
void convert_emb_kernel(const float* __restrict__ emb)
{
    int s = blockIdx.x * 256 + threadIdx.x;
    if (s >= V_SZ * (H_SZ / 4)) return;
    int v  = s >> 7;
    int k4 = (s & 127) << 2;
    float4 x = *(const float4*)(emb + (size_t)v * H_SZ + k4);
    HF4 o;
    o.h[0] = __float2half_rn(x.x);
    o.h[1] = __float2half_rn(x.y);
    o.h[2] = __float2half_rn(x.z);
    o.h[3] = __float2half_rn(x.w);
    *(uint2*)(g_bh + (size_t)v * H_SZ + k4) = o.u;
}

// =====================================================================
// Kernel 3: logits GEMM via mma.sync fp16 (single pass, K=512)
//   CTA 128x128, 256 threads (8 warps 2x4), warp tile 64x32.
//   K chunks of 64 (8 chunks), 3-stage cp.async, SW128 swizzle (128B rows).
// =====================================================================
#define LMT 128
#define LNT 128
#define CHK 64
#define NCH (H_SZ / CHK)         // 8
#define LSTAGES 3
#define TILE_B (128 * 128)       // 128 rows x 128B (64 fp16) = 16384
#define STAGE_B (2 * TILE_B)     // 32768
#define LTOT_B (LSTAGES * STAGE_B)  // 98304

// 128B rows, seg 0..7 (16B units), classic SW128: seg' = seg ^ (row&7).
static __device__ __forceinline__ uint32_t swoff(int row, int seg) {
    return (uint32_t)((row << 7) + (((seg ^ row) & 7) << 4));
}

__global__ __launch_bounds__(256, 2)
void logits_mma_kernel(const float* __restrict__ b_out,
                       float* __restrict__ out)
{
    extern __shared__ __align__(128) char lsm[];
    const uint32_t smb = smem_u32(lsm);
    const int tid  = threadIdx.x;
    const int wid  = tid >> 5;
    const int lane = tid & 31;
    const int warp_m = wid >> 2;   // 0..1 (64 rows)
    const int warp_n = wid & 3;    // 0..3 (32 cols)
    const int m0 = blockIdx.x * LMT;
    const int n0 = blockIdx.y * LNT;

    // loader: 256 threads; thread covers row = tid>>1, segs (tid&1)*4 .. +3
    const int lrw = tid >> 1;          // 0..127
    const int lsb = (tid & 1) * 4;     // 0 or 4

    float c[4][4][4];
#pragma unroll
    for (int i = 0; i < 4; i++)
#pragma unroll
        for (int j = 0; j < 4; j++)
#pragma unroll
            for (int q = 0; q < 4; q++) c[i][j][q] = 0.0f;

    const int lrow = lane & 15;
    const int lkh  = lane >> 4;        // 16B k-half within a 16-k block

    const __half* abase = g_ah + (size_t)m0 * H_SZ;
    const __half* bbase = g_bh + (size_t)n0 * H_SZ;

    auto issue = [&](int ch, int st) {
        uint32_t As = smb + st * STAGE_B;
        uint32_t Bs = As + TILE_B;
        const int kb = ch * CHK;
        const __half* ar = abase + (size_t)lrw * H_SZ + kb;
        const __half* br = bbase + (size_t)lrw * H_SZ + kb;
#pragma unroll
        for (int i2 = 0; i2 < 4; i2++) {
            int seg = lsb + i2;
            cp_async16(As + swoff(lrw, seg), ar + seg * 8);
            cp_async16(Bs + swoff(lrw, seg), br + seg * 8);
        }
    };

    // prologue: chunks 0,1
    issue(0, 0); cp_commit();
    issue(1, 1); cp_commit();

    for (int ch = 0; ch < NCH; ch++) {
        cp_wait1();
        __syncthreads();

        int chn = ch + 2;
        if (chn < NCH) issue(chn, chn % LSTAGES);
        cp_commit();   // empty group keeps wait_group counting aligned

        uint32_t As = smb + (ch % LSTAGES) * STAGE_B;
        uint32_t Bs = As + TILE_B;

#pragma unroll
        for (int ks = 0; ks < 4; ks++) {        // 4 x k16 per 64-k chunk
            const int seg = ks * 2 + lkh;
            uint32_t a[4][4], bf[2][4];
#pragma unroll
            for (int mt = 0; mt < 4; mt++)
                ldsm4(a[mt], As + swoff(warp_m * 64 + mt * 16 + lrow, seg));
#pragma unroll
            for (int ng = 0; ng < 2; ng++)
                ldsm4(bf[ng], Bs + swoff(warp_n * 32 + ng * 16 + lrow, seg));
#pragma unroll
            for (int mt = 0; mt < 4; mt++)
#pragma unroll
                for (int nt = 0; nt < 4; nt++) {
                    uint32_t* bv = bf[nt >> 1];
                    mma16816h(c[mt][nt], a[mt], bv[nt & 1], bv[(nt & 1) + 2]);
                }
        }
        __syncthreads();
    }

    // ---- epilogue ----
    const int rr   = lane >> 2;
    const int col2 = (lane & 3) * 2;
    const int ncol0 = n0 + warp_n * 32;
#pragma unroll
    for (int mt = 0; mt < 4; mt++) {
#pragma unroll
        for (int half = 0; half < 2; half++) {
            int m = m0 + warp_m * 64 + mt * 16 + rr + half * 8;
            int bb2 = m & 31;
            int tt  = m >> 5;
            float* dst = out + ((size_t)bb2 * T_SEQ + tt) * V_SZ + ncol0;
#pragma unroll
            for (int nt = 0; nt < 4; nt++) {
                int nc = nt * 8 + col2;
                float2 v;
                v.x = c[mt][nt][half * 2 + 0] + __ldg(b_out + ncol0 + nc);
                v.y = c[mt][nt][half * 2 + 1] + __ldg(b_out + ncol0 + nc + 1);
                *(float2*)(dst + nc) = v;
            }
        }
    }
}

// =====================================================================
// kernel_launch
// =====================================================================
extern "C" void kernel_launch(void* const* d_in, const int* in_sizes, int n_in,
                              void* d_out, int out_size)
{
    const float* emb    = (const float*)d_in[0];  // [V, H]
    const float* w_ih   = (const float*)d_in[1];  // [3H, H]
    const float* w_hh   = (const float*)d_in[2];  // [3H, H]
    const float* b_ih   = (const float*)d_in[3];  // [3H]
    const float* b_hh   = (const float*)d_in[4];  // [3H]
    const float* b_out  = (const float*)d_in[5];  // [V]
    const float* enc    = (const float*)d_in[6];  // [1, B, H]
    const int*   target = (const int*)d_in[7];    // [B, T]
    float* out = (float*)d_out;                   // [B, T, V]

    (void)in_sizes; (void)n_in; (void)out_size;

    static bool attr_done = false;
    if (!attr_done) {
        cudaFuncSetAttribute(gru_persistent_kernel,
                             cudaFuncAttributeMaxDynamicSharedMemorySize,
                             GRU_SMEM_FLOATS * sizeof(float));
        cudaFuncSetAttribute(logits_mma_kernel,
                             cudaFuncAttributeMaxDynamicSharedMemorySize, LTOT_B);
        attr_done = true;
    }

    convert_emb_kernel<<<(V_SZ * (H_SZ / 4) + 255) / 256, 256>>>(emb);

    embed_xg_kernel<<<dim3(M_ROWS / BM, G3 / BN), 256>>>(emb, w_ih, b_ih, target);

    reset_bar_kernel<<<1, 1>>>();
    gru_persistent_kernel<<<128, 512, GRU_SMEM_FLOATS * sizeof(float)>>>(
        w_hh, b_hh, enc);

    logits_mma_kernel<<<dim3(M_ROWS / LMT, V_SZ / LNT), 256, LTOT_B>>>(b_out, out);
}